// round 10
// baseline (speedup 1.0000x reference)
#include <cuda_runtime.h>
#include <math.h>

static constexpr int NE = 8;
static constexpr int NT = 256;
static constexpr int ND = 2048;
static constexpr int NH = 8192;

// Scratch (__device__ globals: allocation-guard safe)
__device__ float g_s1[(size_t)NE * NT * NH];   // mid (64MB)
__device__ float g_s2[(size_t)NE * NT * ND];   // tf32-rounded x (16MB)

__device__ __forceinline__ unsigned f2tf(float x) {
    unsigned r;
    asm("cvt.rna.tf32.f32 %0, %1;" : "=r"(r) : "f"(x));
    return r;
}

__device__ __forceinline__ float silu(float x) {
    return x / (1.0f + __expf(-x));
}

__device__ __forceinline__ unsigned s2u(const void* p) {
    unsigned a;
    asm("{ .reg .u64 t; cvta.to.shared.u64 t, %1; cvt.u32.u64 %0, t; }" : "=r"(a) : "l"(p));
    return a;
}

__device__ __forceinline__ void cpasync16(unsigned dst, const void* src) {
    asm volatile("cp.async.cg.shared.global [%0], [%1], 16;" :: "r"(dst), "l"(src) : "memory");
}

#define MMA_TF32(ACC, A0, A1, A2, A3, B0, B1)                                  \
    asm volatile(                                                              \
        "mma.sync.aligned.m16n8k8.row.col.f32.tf32.tf32.f32 "                  \
        "{%0,%1,%2,%3}, {%4,%5,%6,%7}, {%8,%9}, {%0,%1,%2,%3};"                \
        : "+f"((ACC)[0]), "+f"((ACC)[1]), "+f"((ACC)[2]), "+f"((ACC)[3])       \
        : "r"(A0), "r"(A1), "r"(A2), "r"(A3), "r"(B0), "r"(B1))

// Elementwise tf32 pre-round (x -> g_s2), float4 vectorized
__global__ void round_tf32(const float* __restrict__ in, float* __restrict__ out, int n4) {
    int i = blockIdx.x * blockDim.x + threadIdx.x;
    if (i < n4) {
        float4 v = ((const float4*)in)[i];
        float4 w;
        w.x = __uint_as_float(f2tf(v.x));
        w.y = __uint_as_float(f2tf(v.y));
        w.z = __uint_as_float(f2tf(v.z));
        w.w = __uint_as_float(f2tf(v.w));
        ((float4*)out)[i] = w;
    }
}

// NOTE on fragment k-permutation (both kernels): within each 8-wide MMA k-group
// the hardware pairs A slot c with B slot c; we map physical slot tig -> logical
// k8+2*tig and slot tig+4 -> logical k8+2*tig+1 (same bijection on A and B), so
// each thread's two k-values are smem-adjacent -> LDS.64.

// ---------------------------------------------------------------------------
// Fused up/gate: mid = round_tf32( silu(x@w1) * (x@w3) )
// A = pre-rounded x [NT, ND]; W1/W3 = [ND, NH] (n contiguous). CTA: 128 x 64.
// ---------------------------------------------------------------------------
__global__ __launch_bounds__(256, 2)
void ffn_fused(const float* __restrict__ A, const float* __restrict__ W1,
               const float* __restrict__ W3, float* __restrict__ Cg)
{
    constexpr int SA = 40;            // A row stride (words): 40g%32=8g -> LDS.64 conflict-free
    constexpr int SBW = 68;           // B row stride: 136*tig%32=8tig -> LDS.32 conflict-free
    constexpr int ASZ = 128 * SA;
    constexpr int BSZ = 32 * SBW;
    constexpr int STG = ASZ + 2 * BSZ;            // floats per stage

    extern __shared__ float sm[];
    const unsigned sbase = s2u(sm);

    const int tid  = threadIdx.x;
    const int wid  = tid >> 5;
    const int lane = tid & 31;
    const int wm   = wid >> 2;        // 0..1
    const int wn   = wid & 3;         // 0..3
    const int g    = lane >> 2;
    const int tig  = lane & 3;

    const int m0 = blockIdx.y * 128;
    const int n0 = blockIdx.x * 64;
    const size_t z = blockIdx.z;

    const float* Ae  = A  + z * (size_t)NT * ND + (size_t)m0 * ND;
    const float* B1e = W1 + z * (size_t)ND * NH;
    const float* B3e = W3 + z * (size_t)ND * NH;
    float*       Ce  = Cg + z * (size_t)NT * NH;

    float acc1[4][2][4], acc3[4][2][4];
    #pragma unroll
    for (int i = 0; i < 4; i++)
        #pragma unroll
        for (int j = 0; j < 2; j++)
            #pragma unroll
            for (int k = 0; k < 4; k++) { acc1[i][j][k] = 0.0f; acc3[i][j][k] = 0.0f; }

    auto stage = [&](int s, int kt) {
        const unsigned ab = sbase + (unsigned)s * STG * 4;
        const unsigned b1 = ab + ASZ * 4;
        const unsigned b3 = b1 + BSZ * 4;
        #pragma unroll
        for (int i = 0; i < 4; i++) {
            int idx = tid + i * 256;
            int r = idx >> 3, c = (idx & 7) * 4;
            cpasync16(ab + (r * SA + c) * 4, Ae + (size_t)r * ND + kt + c);
        }
        #pragma unroll
        for (int i = 0; i < 2; i++) {
            int idx = tid + i * 256;
            int kr = idx >> 4, nc = (idx & 15) * 4;
            cpasync16(b1 + (kr * SBW + nc) * 4, B1e + (size_t)(kt + kr) * NH + n0 + nc);
            cpasync16(b3 + (kr * SBW + nc) * 4, B3e + (size_t)(kt + kr) * NH + n0 + nc);
        }
        asm volatile("cp.async.commit_group;" ::: "memory");
    };

    constexpr int NIT = ND / 32;      // 64
    stage(0, 0);
    stage(1, 32);

    #pragma unroll 1
    for (int it = 0; it < NIT; it++) {
        if (it + 1 < NIT) asm volatile("cp.async.wait_group 1;" ::: "memory");
        else              asm volatile("cp.async.wait_group 0;" ::: "memory");
        __syncthreads();
        if (it + 2 < NIT) stage((it + 2) % 3, (it + 2) * 32);

        const float* As  = sm + (size_t)(it % 3) * STG;
        const float* B1s = As + ASZ;
        const float* B3s = B1s + BSZ;

        #pragma unroll
        for (int ks = 0; ks < 4; ks++) {
            const int k8 = ks * 8;
            const int kk = k8 + 2 * tig;

            float2 a[4][2];
            #pragma unroll
            for (int mi = 0; mi < 4; mi++) {
                int row = wm * 64 + mi * 16 + g;
                a[mi][0] = *(const float2*)&As[row       * SA + kk];
                a[mi][1] = *(const float2*)&As[(row + 8) * SA + kk];
            }
            unsigned b1f[2][2], b3f[2][2];
            #pragma unroll
            for (int nj = 0; nj < 2; nj++) {
                int n = wn * 16 + nj * 8 + g;
                b1f[nj][0] = f2tf(B1s[kk       * SBW + n]);
                b1f[nj][1] = f2tf(B1s[(kk + 1) * SBW + n]);
                b3f[nj][0] = f2tf(B3s[kk       * SBW + n]);
                b3f[nj][1] = f2tf(B3s[(kk + 1) * SBW + n]);
            }
            #pragma unroll
            for (int mi = 0; mi < 4; mi++) {
                unsigned a0 = __float_as_uint(a[mi][0].x);
                unsigned a1 = __float_as_uint(a[mi][1].x);
                unsigned a2 = __float_as_uint(a[mi][0].y);
                unsigned a3 = __float_as_uint(a[mi][1].y);
                #pragma unroll
                for (int nj = 0; nj < 2; nj++) {
                    MMA_TF32(acc1[mi][nj], a0, a1, a2, a3, b1f[nj][0], b1f[nj][1]);
                    MMA_TF32(acc3[mi][nj], a0, a1, a2, a3, b3f[nj][0], b3f[nj][1]);
                }
            }
        }
    }

    // epilogue: mid = round(silu(h1) * h3), tf32-rounded for GEMM3's A
    #pragma unroll
    for (int mi = 0; mi < 4; mi++) {
        #pragma unroll
        for (int nj = 0; nj < 2; nj++) {
            int row = m0 + wm * 64 + mi * 16 + g;
            int col = n0 + wn * 16 + nj * 8 + 2 * tig;
            float2 v0, v1;
            v0.x = __uint_as_float(f2tf(silu(acc1[mi][nj][0]) * acc3[mi][nj][0]));
            v0.y = __uint_as_float(f2tf(silu(acc1[mi][nj][1]) * acc3[mi][nj][1]));
            v1.x = __uint_as_float(f2tf(silu(acc1[mi][nj][2]) * acc3[mi][nj][2]));
            v1.y = __uint_as_float(f2tf(silu(acc1[mi][nj][3]) * acc3[mi][nj][3]));
            *(float2*)&Ce[(size_t)row * NH + col]       = v0;
            *(float2*)&Ce[(size_t)(row + 8) * NH + col] = v1;
        }
    }
}

// ---------------------------------------------------------------------------
// Down proj: out[T, D] = mid[T, H] @ w2[D, H]^T.  A pre-rounded; B k-contig.
// CTA: 128 x 128, 2-stage cp.async pipeline.
// ---------------------------------------------------------------------------
__global__ __launch_bounds__(256, 2)
void gemm_down(const float* __restrict__ A, const float* __restrict__ Bg,
               float* __restrict__ Cg)
{
    constexpr int SA = 40;
    constexpr int SB = 40;            // n rows, k contig: 40g%32=8g -> LDS.64 conflict-free
    constexpr int ASZ = 128 * SA;
    constexpr int BSZ = 128 * SB;
    constexpr int STG = ASZ + BSZ;

    extern __shared__ float sm[];
    const unsigned sbase = s2u(sm);

    const int tid  = threadIdx.x;
    const int wid  = tid >> 5;
    const int lane = tid & 31;
    const int wm   = wid >> 2;
    const int wn   = wid & 3;
    const int g    = lane >> 2;
    const int tig  = lane & 3;

    const int m0 = blockIdx.y * 128;
    const int n0 = blockIdx.x * 128;
    const size_t z = blockIdx.z;

    const float* Ae = A  + z * (size_t)NT * NH + (size_t)m0 * NH;
    const float* Be = Bg + z * (size_t)ND * NH;
    float*       Ce = Cg + z * (size_t)NT * ND;

    float acc[4][4][4];
    #pragma unroll
    for (int i = 0; i < 4; i++)
        #pragma unroll
        for (int j = 0; j < 4; j++)
            #pragma unroll
            for (int k = 0; k < 4; k++)
                acc[i][j][k] = 0.0f;

    auto stage = [&](int s, int kt) {
        const unsigned ab = sbase + (unsigned)s * STG * 4;
        const unsigned bb = ab + ASZ * 4;
        #pragma unroll
        for (int i = 0; i < 4; i++) {
            int idx = tid + i * 256;
            int r = idx >> 3, c = (idx & 7) * 4;
            cpasync16(ab + (r * SA + c) * 4, Ae + (size_t)r * NH + kt + c);
        }
        #pragma unroll
        for (int i = 0; i < 4; i++) {
            int idx = tid + i * 256;
            int nr = idx >> 3, kc = (idx & 7) * 4;
            cpasync16(bb + (nr * SB + kc) * 4, Be + (size_t)(n0 + nr) * NH + kt + kc);
        }
        asm volatile("cp.async.commit_group;" ::: "memory");
    };

    constexpr int NIT = NH / 32;      // 256
    stage(0, 0);
    stage(1, 32);

    #pragma unroll 1
    for (int it = 0; it < NIT; it++) {
        if (it + 1 < NIT) asm volatile("cp.async.wait_group 1;" ::: "memory");
        else              asm volatile("cp.async.wait_group 0;" ::: "memory");
        __syncthreads();

        const float* As = sm + (size_t)(it & 1) * STG;
        const float* Bs = As + ASZ;

        #pragma unroll
        for (int ks = 0; ks < 4; ks++) {
            const int k8 = ks * 8;
            const int kk = k8 + 2 * tig;

            float2 a[4][2];
            #pragma unroll
            for (int mi = 0; mi < 4; mi++) {
                int row = wm * 64 + mi * 16 + g;
                a[mi][0] = *(const float2*)&As[row       * SA + kk];
                a[mi][1] = *(const float2*)&As[(row + 8) * SA + kk];
            }
            unsigned bf[4][2];
            #pragma unroll
            for (int nj = 0; nj < 4; nj++) {
                int n = wn * 32 + nj * 8 + g;
                float2 bp = *(const float2*)&Bs[n * SB + kk];
                bf[nj][0] = f2tf(bp.x);
                bf[nj][1] = f2tf(bp.y);
            }
            #pragma unroll
            for (int mi = 0; mi < 4; mi++) {
                unsigned a0 = __float_as_uint(a[mi][0].x);
                unsigned a1 = __float_as_uint(a[mi][1].x);
                unsigned a2 = __float_as_uint(a[mi][0].y);
                unsigned a3 = __float_as_uint(a[mi][1].y);
                #pragma unroll
                for (int nj = 0; nj < 4; nj++)
                    MMA_TF32(acc[mi][nj], a0, a1, a2, a3, bf[nj][0], bf[nj][1]);
            }
        }

        if (it + 2 < NIT) {
            __syncthreads();                  // all warps done reading buffer it&1
            stage(it & 1, (it + 2) * 32);
        }
    }

    #pragma unroll
    for (int mi = 0; mi < 4; mi++) {
        #pragma unroll
        for (int nj = 0; nj < 4; nj++) {
            int row = m0 + wm * 64 + mi * 16 + g;
            int col = n0 + wn * 32 + nj * 8 + 2 * tig;
            float2 v0, v1;
            v0.x = acc[mi][nj][0];
            v0.y = acc[mi][nj][1];
            v1.x = acc[mi][nj][2];
            v1.y = acc[mi][nj][3];
            *(float2*)&Ce[(size_t)row * ND + col]       = v0;
            *(float2*)&Ce[(size_t)(row + 8) * ND + col] = v1;
        }
    }
}

extern "C" void kernel_launch(void* const* d_in, const int* in_sizes, int n_in,
                              void* d_out, int out_size)
{
    const float* x  = (const float*)d_in[0];
    const float* w1 = (const float*)d_in[1];
    const float* w2 = (const float*)d_in[2];
    const float* w3 = (const float*)d_in[3];
    float* out = (float*)d_out;

    float* s1 = nullptr;
    float* s2 = nullptr;
    cudaGetSymbolAddress((void**)&s1, g_s1);   // no allocation; capture-safe
    cudaGetSymbolAddress((void**)&s2, g_s2);

    constexpr size_t SMF = 3 * (size_t)(128 * 40 + 2 * 32 * 68) * sizeof(float);   // 113664
    constexpr size_t SMD = 2 * (size_t)(128 * 40 + 128 * 40) * sizeof(float);      // 81920
    cudaFuncSetAttribute(ffn_fused, cudaFuncAttributeMaxDynamicSharedMemorySize, SMF);
    cudaFuncSetAttribute(gemm_down, cudaFuncAttributeMaxDynamicSharedMemorySize, SMD);

    dim3 blk(256);
    dim3 gf(NH / 64, NT / 128, NE);    // (128, 2, 8)
    dim3 gd(ND / 128, NT / 128, NE);   // (16, 2, 8)

    // 0) pre-round x to tf32
    int n4 = NE * NT * ND / 4;
    round_tf32<<<(n4 + 255) / 256, 256>>>(x, s2, n4);

    // 1) mid = round(silu(x@w1) * (x@w3))   -> s1   (h1 never materialized)
    ffn_fused<<<gf, blk, SMF>>>(s2, w1, w3, s1);

    // 2) out = mid @ w2^T
    gemm_down<<<gd, blk, SMD>>>(s1, w2, out);
}